// round 5
// baseline (speedup 1.0000x reference)
#include <cuda_runtime.h>
#include <cuda_bf16.h>

// CumAvgPool1d: y[..., t] = cumsum(x)[..., t] / (t+1)
// x: (8, 512, 16384) fp32 -> 4096 rows of T=16384.
//
// R4: warp-per-row, zero barriers, 8 elems/lane per chunk.
// Row = 64 chunks of 256 elems; each lane owns 8 contiguous floats
// (2 float4) per chunk. One 5-step shuffle scan per 256 elems (2x fewer
// scan instrs per byte than R3). Divisors generated with incremental
// float adds (no I2F in loop). Depth-2 chunk prefetch ring keeps
// 4 LDG.128/lane in flight. Streaming cache hints (zero reuse).

constexpr int T_LEN  = 16384;
constexpr int T_F4   = T_LEN / 4;       // 4096 float4 per row
constexpr int CHUNK_ELEMS = 256;        // per-warp chunk
constexpr int CHUNK_F4    = CHUNK_ELEMS / 4;   // 64 float4
constexpr int CHUNKS = T_LEN / CHUNK_ELEMS;    // 64
constexpr int WARPS_PER_CTA = 4;
constexpr int THREADS = WARPS_PER_CTA * 32;
constexpr int PF = 2;                   // prefetch depth in chunks

__global__ void __launch_bounds__(THREADS)
cumavg_kernel(const float4* __restrict__ x, float4* __restrict__ y, int rows)
{
    const int lane = threadIdx.x & 31;
    const int warp = threadIdx.x >> 5;
    const int row  = blockIdx.x * WARPS_PER_CTA + warp;
    if (row >= rows) return;

    const float4* px = x + (size_t)row * T_F4;
    float4*       py = y + (size_t)row * T_F4;

    // lane's float4 slot within a chunk: 2 consecutive float4 per lane
    const int lslot = lane * 2;

    // prefetch ring: chunks 0..PF-1 (2 float4 each)
    float4 bufa[PF], bufb[PF];
    #pragma unroll
    for (int i = 0; i < PF; ++i) {
        bufa[i] = __ldcs(px + i * CHUNK_F4 + lslot);
        bufb[i] = __ldcs(px + i * CHUNK_F4 + lslot + 1);
    }

    float carry = 0.0f;
    // float divisor base for this lane: t0 = c*256 + lane*8 (exact in fp32)
    float tb = (float)(lane * 8);

    #pragma unroll 2
    for (int c = 0; c < CHUNKS; ++c) {
        float4 a = bufa[c & (PF - 1)];
        float4 b = bufb[c & (PF - 1)];
        // refill slot with chunk c+PF
        if (c + PF < CHUNKS) {
            bufa[c & (PF - 1)] = __ldcs(px + (c + PF) * CHUNK_F4 + lslot);
            bufb[c & (PF - 1)] = __ldcs(px + (c + PF) * CHUNK_F4 + lslot + 1);
        }

        // thread-local inclusive scan of 8 contiguous elements
        float r = a.x;  a.x = r;
        r += a.y;       a.y = r;
        r += a.z;       a.z = r;
        r += a.w;       a.w = r;
        r += b.x;       b.x = r;
        r += b.y;       b.y = r;
        r += b.z;       b.z = r;
        r += b.w;       b.w = r;

        // warp inclusive scan of per-lane totals
        float wval = r;
        #pragma unroll
        for (int d = 1; d < 32; d <<= 1) {
            float n = __shfl_up_sync(0xffffffffu, wval, d);
            if (lane >= d) wval += n;
        }

        const float off   = carry + (wval - r);               // exclusive prefix
        const float total = __shfl_sync(0xffffffffu, wval, 31);

        // y[t] = (off + local) / (t+1); divisors via float adds (exact ints)
        float4 o;
        o.x = (off + a.x) * __fdividef(1.0f, tb + 1.0f);
        o.y = (off + a.y) * __fdividef(1.0f, tb + 2.0f);
        o.z = (off + a.z) * __fdividef(1.0f, tb + 3.0f);
        o.w = (off + a.w) * __fdividef(1.0f, tb + 4.0f);
        __stcs(py + c * CHUNK_F4 + lslot, o);

        o.x = (off + b.x) * __fdividef(1.0f, tb + 5.0f);
        o.y = (off + b.y) * __fdividef(1.0f, tb + 6.0f);
        o.z = (off + b.z) * __fdividef(1.0f, tb + 7.0f);
        o.w = (off + b.w) * __fdividef(1.0f, tb + 8.0f);
        __stcs(py + c * CHUNK_F4 + lslot + 1, o);

        carry += total;
        tb += (float)CHUNK_ELEMS;
    }
}

extern "C" void kernel_launch(void* const* d_in, const int* in_sizes, int n_in,
                              void* d_out, int out_size)
{
    const float* x = (const float*)d_in[0];
    float*       y = (float*)d_out;
    const int total = in_sizes[0];
    const int rows  = total / T_LEN;   // 4096 for the reference shape

    const int ctas = (rows + WARPS_PER_CTA - 1) / WARPS_PER_CTA;
    cumavg_kernel<<<ctas, THREADS>>>((const float4*)x, (float4*)y, rows);
}

// round 6
// speedup vs baseline: 1.0232x; 1.0232x over previous
#include <cuda_runtime.h>
#include <cuda_bf16.h>

// CumAvgPool1d: y[..., t] = cumsum(x)[..., t] / (t+1)
// x: (8, 512, 16384) fp32 -> 4096 rows of T=16384.
//
// R5: warp-per-row, zero barriers. 8 elems/lane per chunk (64 chunks of 256)
// for low per-byte instruction overhead (R4), combined with a DEPTH-4 chunk
// prefetch ring (R3's latency hiding, doubled): 8 LDG.128/lane in flight,
// 4 KB/warp, issue-to-use distance ~800 cyc > loaded DRAM latency.
// Divisors via incremental float adds (exact for ints < 2^24).
// Streaming cache hints: zero reuse.

constexpr int T_LEN  = 16384;
constexpr int T_F4   = T_LEN / 4;              // 4096 float4 per row
constexpr int CHUNK_ELEMS = 256;               // per-warp chunk
constexpr int CHUNK_F4    = CHUNK_ELEMS / 4;   // 64 float4
constexpr int CHUNKS = T_LEN / CHUNK_ELEMS;    // 64
constexpr int WARPS_PER_CTA = 4;
constexpr int THREADS = WARPS_PER_CTA * 32;
constexpr int PF = 4;                          // prefetch depth in chunks

__global__ void __launch_bounds__(THREADS)
cumavg_kernel(const float4* __restrict__ x, float4* __restrict__ y, int rows)
{
    const int lane = threadIdx.x & 31;
    const int warp = threadIdx.x >> 5;
    const int row  = blockIdx.x * WARPS_PER_CTA + warp;
    if (row >= rows) return;

    const float4* px = x + (size_t)row * T_F4;
    float4*       py = y + (size_t)row * T_F4;

    // lane's float4 slot within a chunk: 2 consecutive float4 per lane
    const int lslot = lane * 2;

    // prefetch ring: chunks 0..PF-1, 2 float4 each -> 8 LDG.128 in flight
    float4 bufa[PF], bufb[PF];
    #pragma unroll
    for (int i = 0; i < PF; ++i) {
        bufa[i] = __ldcs(px + i * CHUNK_F4 + lslot);
        bufb[i] = __ldcs(px + i * CHUNK_F4 + lslot + 1);
    }

    float carry = 0.0f;
    // divisor base for this lane: t0 = c*256 + lane*8 (exact in fp32)
    float tb = (float)(lane * 8);

    #pragma unroll 4
    for (int c = 0; c < CHUNKS; ++c) {
        float4 a = bufa[c & (PF - 1)];
        float4 b = bufb[c & (PF - 1)];
        // refill this slot with chunk c+PF (keeps ring full)
        if (c + PF < CHUNKS) {
            bufa[c & (PF - 1)] = __ldcs(px + (c + PF) * CHUNK_F4 + lslot);
            bufb[c & (PF - 1)] = __ldcs(px + (c + PF) * CHUNK_F4 + lslot + 1);
        }

        // thread-local inclusive scan of 8 contiguous elements
        float r = a.x;  a.x = r;
        r += a.y;       a.y = r;
        r += a.z;       a.z = r;
        r += a.w;       a.w = r;
        r += b.x;       b.x = r;
        r += b.y;       b.y = r;
        r += b.z;       b.z = r;
        r += b.w;       b.w = r;

        // warp inclusive scan of per-lane totals
        float wval = r;
        #pragma unroll
        for (int d = 1; d < 32; d <<= 1) {
            float n = __shfl_up_sync(0xffffffffu, wval, d);
            if (lane >= d) wval += n;
        }

        const float off   = carry + (wval - r);               // exclusive prefix
        const float total = __shfl_sync(0xffffffffu, wval, 31);

        // y[t] = (off + local) / (t+1)
        float4 o;
        o.x = (off + a.x) * __fdividef(1.0f, tb + 1.0f);
        o.y = (off + a.y) * __fdividef(1.0f, tb + 2.0f);
        o.z = (off + a.z) * __fdividef(1.0f, tb + 3.0f);
        o.w = (off + a.w) * __fdividef(1.0f, tb + 4.0f);
        __stcs(py + c * CHUNK_F4 + lslot, o);

        o.x = (off + b.x) * __fdividef(1.0f, tb + 5.0f);
        o.y = (off + b.y) * __fdividef(1.0f, tb + 6.0f);
        o.z = (off + b.z) * __fdividef(1.0f, tb + 7.0f);
        o.w = (off + b.w) * __fdividef(1.0f, tb + 8.0f);
        __stcs(py + c * CHUNK_F4 + lslot + 1, o);

        carry += total;
        tb += (float)CHUNK_ELEMS;
    }
}

extern "C" void kernel_launch(void* const* d_in, const int* in_sizes, int n_in,
                              void* d_out, int out_size)
{
    const float* x = (const float*)d_in[0];
    float*       y = (float*)d_out;
    const int total = in_sizes[0];
    const int rows  = total / T_LEN;   // 4096 for the reference shape

    const int ctas = (rows + WARPS_PER_CTA - 1) / WARPS_PER_CTA;
    cumavg_kernel<<<ctas, THREADS>>>((const float4*)x, (float4*)y, rows);
}

// round 7
// speedup vs baseline: 1.0879x; 1.0633x over previous
#include <cuda_runtime.h>
#include <cuda_bf16.h>

// CumAvgPool1d: y[..., t] = cumsum(x)[..., t] / (t+1)
// x: (8, 512, 16384) fp32 -> 4096 rows of T=16384.
//
// R6: warp-per-row, zero barriers. 256-elem chunks BUT with per-instruction
// contiguous loads: lane loads f4[c*64 + lane] (512B contiguous) and
// f4[c*64 + 32 + lane] (next 512B) -- every LDG.128/STG.128 is
// sector-perfect (R3's memory pattern) while loop/carry overhead is paid
// per 256 elems (R4's amortization). Two independent shuffle scans per
// chunk (sub-halves A,B) interleave for ILP. PF=4 chunk ring = 8 clean
// LDG.128/lane in flight. Streaming hints: zero reuse.

constexpr int T_LEN  = 16384;
constexpr int T_F4   = T_LEN / 4;              // 4096 float4 per row
constexpr int CHUNK_F4 = 64;                   // 256 elems per chunk
constexpr int CHUNKS = T_F4 / CHUNK_F4;        // 64
constexpr int WARPS_PER_CTA = 4;
constexpr int THREADS = WARPS_PER_CTA * 32;
constexpr int PF = 4;                          // prefetch depth in chunks

__global__ void __launch_bounds__(THREADS)
cumavg_kernel(const float4* __restrict__ x, float4* __restrict__ y, int rows)
{
    const int lane = threadIdx.x & 31;
    const int warp = threadIdx.x >> 5;
    const int row  = blockIdx.x * WARPS_PER_CTA + warp;
    if (row >= rows) return;

    const float4* px = x + (size_t)row * T_F4;
    float4*       py = y + (size_t)row * T_F4;

    // prefetch ring: chunks 0..PF-1; each chunk = two contiguous 512B halves
    float4 bufa[PF], bufb[PF];
    #pragma unroll
    for (int i = 0; i < PF; ++i) {
        bufa[i] = __ldcs(px + i * CHUNK_F4 + lane);        // first  128 elems
        bufb[i] = __ldcs(px + i * CHUNK_F4 + 32 + lane);   // second 128 elems
    }

    float carry = 0.0f;
    // divisor bases (exact integer floats): A-half t0 = c*256 + lane*4
    float tba = (float)(lane * 4);
    // B-half t0 = c*256 + 128 + lane*4

    #pragma unroll 4
    for (int c = 0; c < CHUNKS; ++c) {
        float4 a = bufa[c & (PF - 1)];
        float4 b = bufb[c & (PF - 1)];
        if (c + PF < CHUNKS) {
            bufa[c & (PF - 1)] = __ldcs(px + (c + PF) * CHUNK_F4 + lane);
            bufb[c & (PF - 1)] = __ldcs(px + (c + PF) * CHUNK_F4 + 32 + lane);
        }

        // two independent local scans (4 elems each)
        float ra = a.x;  a.x = ra;
        ra += a.y;       a.y = ra;
        ra += a.z;       a.z = ra;
        ra += a.w;       a.w = ra;

        float rb = b.x;  b.x = rb;
        rb += b.y;       b.y = rb;
        rb += b.z;       b.z = rb;
        rb += b.w;       b.w = rb;

        // two independent warp scans -- chains interleave (ILP 2)
        float wa = ra, wb = rb;
        #pragma unroll
        for (int d = 1; d < 32; d <<= 1) {
            float na = __shfl_up_sync(0xffffffffu, wa, d);
            float nb = __shfl_up_sync(0xffffffffu, wb, d);
            if (lane >= d) { wa += na; wb += nb; }
        }

        const float totalA = __shfl_sync(0xffffffffu, wa, 31);
        const float totalB = __shfl_sync(0xffffffffu, wb, 31);
        const float offA = carry + (wa - ra);            // exclusive prefix, A half
        const float offB = carry + totalA + (wb - rb);   // exclusive prefix, B half

        // y[t] = (off + local) / (t+1); divisors via float adds
        float4 o;
        o.x = (offA + a.x) * __fdividef(1.0f, tba + 1.0f);
        o.y = (offA + a.y) * __fdividef(1.0f, tba + 2.0f);
        o.z = (offA + a.z) * __fdividef(1.0f, tba + 3.0f);
        o.w = (offA + a.w) * __fdividef(1.0f, tba + 4.0f);
        __stcs(py + c * CHUNK_F4 + lane, o);

        o.x = (offB + b.x) * __fdividef(1.0f, tba + 129.0f);
        o.y = (offB + b.y) * __fdividef(1.0f, tba + 130.0f);
        o.z = (offB + b.z) * __fdividef(1.0f, tba + 131.0f);
        o.w = (offB + b.w) * __fdividef(1.0f, tba + 132.0f);
        __stcs(py + c * CHUNK_F4 + 32 + lane, o);

        carry += totalA + totalB;
        tba += 256.0f;
    }
}

extern "C" void kernel_launch(void* const* d_in, const int* in_sizes, int n_in,
                              void* d_out, int out_size)
{
    const float* x = (const float*)d_in[0];
    float*       y = (float*)d_out;
    const int total = in_sizes[0];
    const int rows  = total / T_LEN;   // 4096 for the reference shape

    const int ctas = (rows + WARPS_PER_CTA - 1) / WARPS_PER_CTA;
    cumavg_kernel<<<ctas, THREADS>>>((const float4*)x, (float4*)y, rows);
}

// round 9
// speedup vs baseline: 1.1867x; 1.0908x over previous
#include <cuda_runtime.h>
#include <cuda_bf16.h>

// CumAvgPool1d: y[..., t] = cumsum(x)[..., t] / (t+1)
// x: (8, 512, 16384) fp32 -> 4096 rows of T=16384.
//
// R7: CTA-per-row, 4 warps chunk-cyclic with smem carry relay.
// Row = 64 chunks of 256 elems; warp w owns chunks w, w+4, w+8, ...
// The CTA's concurrent DRAM footprint is ONE contiguous ~8-16KB window per
// row (vs 4 scattered 64KB-apart streams in warp-per-row), cutting chip-wide
// stream count 4x for better DRAM row-buffer locality. Carry crosses warps
// via a packed {flag,prefix} 8-byte smem word per chunk (STS.64 publish /
// LDS.64 spin) -- no __syncthreads in the loop; loads are carry-independent
// and run ahead through a depth-2 per-warp ring. Loads/stores sector-perfect
// (512B contiguous per instruction). Streaming hints: zero reuse.

constexpr int T_LEN  = 16384;
constexpr int T_F4   = T_LEN / 4;          // 4096 float4 per row
constexpr int CHUNK_F4 = 64;               // 256 elems
constexpr int CHUNKS = T_F4 / CHUNK_F4;    // 64
constexpr int WARPS  = 4;
constexpr int THREADS = WARPS * 32;
constexpr int CPW = CHUNKS / WARPS;        // 16 chunks per warp

__device__ __forceinline__ unsigned long long pack_rel(float p) {
    return (1ULL << 32) | (unsigned long long)__float_as_uint(p);
}

__global__ void __launch_bounds__(THREADS)
cumavg_kernel(const float4* __restrict__ x, float4* __restrict__ y)
{
    __shared__ unsigned long long relay[CHUNKS + 1];

    const int tid  = threadIdx.x;
    const int lane = tid & 31;
    const int warp = tid >> 5;
    const int row  = blockIdx.x;

    // init relay: slots 1..CHUNKS zero; slot 0 = {flag=1, prefix=0}
    for (int i = tid + 1; i <= CHUNKS; i += THREADS) relay[i] = 0ULL;
    if (tid == 0) relay[0] = pack_rel(0.0f);
    __syncthreads();     // only barrier in the kernel

    const float4* px = x + (size_t)row * T_F4;
    float4*       py = y + (size_t)row * T_F4;

    // depth-2 prefetch ring over this warp's chunk sequence (stride 4 chunks)
    float4 ra4[2], rb4[2];
    {
        const int c0 = warp;
        const int c1 = warp + WARPS;
        ra4[0] = __ldcs(px + c0 * CHUNK_F4 + lane);
        rb4[0] = __ldcs(px + c0 * CHUNK_F4 + 32 + lane);
        ra4[1] = __ldcs(px + c1 * CHUNK_F4 + lane);
        rb4[1] = __ldcs(px + c1 * CHUNK_F4 + 32 + lane);
    }

    // divisor base (exact integer floats): chunk c => t0 = c*256 + lane*4
    float tba = (float)(warp * 256 + lane * 4);

    volatile unsigned long long* vrelay = relay;

    #pragma unroll 2
    for (int k = 0; k < CPW; ++k) {
        const int c = warp + WARPS * k;

        float4 a = ra4[k & 1];
        float4 b = rb4[k & 1];
        if (k + 2 < CPW) {
            const int cn = c + 2 * WARPS;
            ra4[k & 1] = __ldcs(px + cn * CHUNK_F4 + lane);
            rb4[k & 1] = __ldcs(px + cn * CHUNK_F4 + 32 + lane);
        }

        // two independent local scans (4 elems each)
        float rA = a.x;  a.x = rA;
        rA += a.y;       a.y = rA;
        rA += a.z;       a.z = rA;
        rA += a.w;       a.w = rA;

        float rB = b.x;  b.x = rB;
        rB += b.y;       b.y = rB;
        rB += b.z;       b.z = rB;
        rB += b.w;       b.w = rB;

        // two interleaved warp scans (ILP 2)
        float wA = rA, wB = rB;
        #pragma unroll
        for (int d = 1; d < 32; d <<= 1) {
            float nA = __shfl_up_sync(0xffffffffu, wA, d);
            float nB = __shfl_up_sync(0xffffffffu, wB, d);
            if (lane >= d) { wA += nA; wB += nB; }
        }

        const float totalA = __shfl_sync(0xffffffffu, wA, 31);
        const float totalB = __shfl_sync(0xffffffffu, wB, 31);

        // wait for prefix of chunk c (all lanes spin on same 8B -> broadcast)
        unsigned long long v;
        do { v = vrelay[c]; } while ((unsigned)(v >> 32) == 0u);
        const float P = __uint_as_float((unsigned)v);

        // publish prefix for chunk c+1 ASAP (chain-critical)
        if (lane == 0) vrelay[c + 1] = pack_rel(P + totalA + totalB);

        const float offA = P + (wA - rA);            // exclusive prefix, A half
        const float offB = P + totalA + (wB - rB);   // exclusive prefix, B half

        // y[t] = (off + local) / (t+1); divisors via float adds (exact ints)
        float4 o;
        o.x = (offA + a.x) * __fdividef(1.0f, tba + 1.0f);
        o.y = (offA + a.y) * __fdividef(1.0f, tba + 2.0f);
        o.z = (offA + a.z) * __fdividef(1.0f, tba + 3.0f);
        o.w = (offA + a.w) * __fdividef(1.0f, tba + 4.0f);
        __stcs(py + c * CHUNK_F4 + lane, o);

        o.x = (offB + b.x) * __fdividef(1.0f, tba + 129.0f);
        o.y = (offB + b.y) * __fdividef(1.0f, tba + 130.0f);
        o.z = (offB + b.z) * __fdividef(1.0f, tba + 131.0f);
        o.w = (offB + b.w) * __fdividef(1.0f, tba + 132.0f);
        __stcs(py + c * CHUNK_F4 + 32 + lane, o);

        tba += (float)(WARPS * 256);   // next owned chunk is 1024 elems ahead
    }
}

extern "C" void kernel_launch(void* const* d_in, const int* in_sizes, int n_in,
                              void* d_out, int out_size)
{
    const float* x = (const float*)d_in[0];
    float*       y = (float*)d_out;
    const int total = in_sizes[0];
    const int rows  = total / T_LEN;   // 4096 for the reference shape

    cumavg_kernel<<<rows, THREADS>>>((const float4*)x, (float4*)y);
}

// round 10
// speedup vs baseline: 1.2342x; 1.0400x over previous
#include <cuda_runtime.h>
#include <cuda_bf16.h>

// CumAvgPool1d: y[..., t] = cumsum(x)[..., t] / (t+1)
// x: (8, 512, 16384) fp32 -> 4096 rows of T=16384.
//
// R9: CTA-per-row, 8 warps, chunk-cyclic, PARALLEL total-publication relay.
// Row = 64 chunks of 256 elems; round k = chunks 8k..8k+7, one per warp.
// Each warp publishes its chunk TOTAL (flag-packed 8B smem word) right after
// its shuffle scan -- totals have no cross-chunk dependency, so all 8 warps
// publish concurrently; the old serial prefix chain (64 links/row) becomes
// 8 parallel rounds. Each warp gathers the round's 8 totals via one spin +
// shuffles, accumulates carry locally, and derives its prefix.
// Loads/stores sector-perfect (512B contiguous per instruction); depth-2
// prefetch ring; streaming hints (zero reuse). No __syncthreads in loop.

constexpr int T_LEN  = 16384;
constexpr int T_F4   = T_LEN / 4;          // 4096 float4 per row
constexpr int CHUNK_F4 = 64;               // 256 elems per chunk
constexpr int CHUNKS = T_F4 / CHUNK_F4;    // 64
constexpr int WARPS  = 8;
constexpr int THREADS = WARPS * 32;        // 256
constexpr int ROUNDS = CHUNKS / WARPS;     // 8

__device__ __forceinline__ unsigned long long pack_rel(float p) {
    return (1ULL << 32) | (unsigned long long)__float_as_uint(p);
}

__global__ void __launch_bounds__(THREADS)
cumavg_kernel(const float4* __restrict__ x, float4* __restrict__ y)
{
    __shared__ unsigned long long relay[CHUNKS];

    const int tid  = threadIdx.x;
    const int lane = tid & 31;
    const int warp = tid >> 5;
    const int row  = blockIdx.x;

    for (int i = tid; i < CHUNKS; i += THREADS) relay[i] = 0ULL;
    __syncthreads();     // only barrier in the kernel

    const float4* px = x + (size_t)row * T_F4;
    float4*       py = y + (size_t)row * T_F4;

    // depth-2 prefetch ring over this warp's chunks (w, w+8, w+16, ...)
    float4 ra4[2], rb4[2];
    {
        const int c0 = warp;
        const int c1 = warp + WARPS;
        ra4[0] = __ldcs(px + c0 * CHUNK_F4 + lane);
        rb4[0] = __ldcs(px + c0 * CHUNK_F4 + 32 + lane);
        ra4[1] = __ldcs(px + c1 * CHUNK_F4 + lane);
        rb4[1] = __ldcs(px + c1 * CHUNK_F4 + 32 + lane);
    }

    float carry = 0.0f;
    // divisor base (exact integer floats): chunk c => t0 = c*256 + lane*4
    float tba = (float)(warp * 256 + lane * 4);

    volatile unsigned long long* vrelay = relay;

    #pragma unroll 2
    for (int k = 0; k < ROUNDS; ++k) {
        const int c = warp + WARPS * k;

        float4 a = ra4[k & 1];
        float4 b = rb4[k & 1];
        if (k + 2 < ROUNDS) {
            const int cn = c + 2 * WARPS;
            ra4[k & 1] = __ldcs(px + cn * CHUNK_F4 + lane);
            rb4[k & 1] = __ldcs(px + cn * CHUNK_F4 + 32 + lane);
        }

        // two independent local scans (4 elems each)
        float rA = a.x;  a.x = rA;
        rA += a.y;       a.y = rA;
        rA += a.z;       a.z = rA;
        rA += a.w;       a.w = rA;

        float rB = b.x;  b.x = rB;
        rB += b.y;       b.y = rB;
        rB += b.z;       b.z = rB;
        rB += b.w;       b.w = rB;

        // two interleaved warp scans (ILP 2)
        float wA = rA, wB = rB;
        #pragma unroll
        for (int d = 1; d < 32; d <<= 1) {
            float nA = __shfl_up_sync(0xffffffffu, wA, d);
            float nB = __shfl_up_sync(0xffffffffu, wB, d);
            if (lane >= d) { wA += nA; wB += nB; }
        }

        const float totalA = __shfl_sync(0xffffffffu, wA, 31);
        const float totalB = __shfl_sync(0xffffffffu, wB, 31);

        // publish this chunk's TOTAL immediately (no cross-chunk dependency)
        if (lane == 0) vrelay[c] = pack_rel(totalA + totalB);

        // wait for all 8 totals of this round (lane j<8 watches slot 8k+j)
        const int slot = WARPS * k + (lane & (WARPS - 1));
        unsigned long long v;
        unsigned m;
        do {
            v = vrelay[slot];
            m = __ballot_sync(0xffffffffu, (unsigned)(v >> 32) != 0u);
        } while ((m & 0xFFu) != 0xFFu);
        const float tj = __uint_as_float((unsigned)v);   // lane j: total of chunk 8k+j

        // prefix over earlier chunks in this round + carry over earlier rounds
        float pre = 0.0f, all = 0.0f;
        #pragma unroll
        for (int j = 0; j < WARPS; ++j) {
            const float t = __shfl_sync(0xffffffffu, tj, j);
            all += t;
            if (j < warp) pre += t;
        }

        const float P = carry + pre;
        carry += all;

        const float offA = P + (wA - rA);            // exclusive prefix, A half
        const float offB = P + totalA + (wB - rB);   // exclusive prefix, B half

        // y[t] = (off + local) / (t+1); divisors via float adds (exact ints)
        float4 o;
        o.x = (offA + a.x) * __fdividef(1.0f, tba + 1.0f);
        o.y = (offA + a.y) * __fdividef(1.0f, tba + 2.0f);
        o.z = (offA + a.z) * __fdividef(1.0f, tba + 3.0f);
        o.w = (offA + a.w) * __fdividef(1.0f, tba + 4.0f);
        __stcs(py + c * CHUNK_F4 + lane, o);

        o.x = (offB + b.x) * __fdividef(1.0f, tba + 129.0f);
        o.y = (offB + b.y) * __fdividef(1.0f, tba + 130.0f);
        o.z = (offB + b.z) * __fdividef(1.0f, tba + 131.0f);
        o.w = (offB + b.w) * __fdividef(1.0f, tba + 132.0f);
        __stcs(py + c * CHUNK_F4 + 32 + lane, o);

        tba += (float)(WARPS * 256);   // next owned chunk is 2048 elems ahead
    }
}

extern "C" void kernel_launch(void* const* d_in, const int* in_sizes, int n_in,
                              void* d_out, int out_size)
{
    const float* x = (const float*)d_in[0];
    float*       y = (float*)d_out;
    const int total = in_sizes[0];
    const int rows  = total / T_LEN;   // 4096 for the reference shape

    cumavg_kernel<<<rows, THREADS>>>((const float4*)x, (float4*)y);
}